// round 13
// baseline (speedup 1.0000x reference)
#include <cuda_runtime.h>
#include <math.h>

// ---------------------------------------------------------------------------
// Problem constants (B=4, S=4096, D=1024, H=4096)
// ---------------------------------------------------------------------------
#define MROWS 16384          // B*S
#define DMODEL 1024
#define HDIM   4096
#define SEQ    4096
#define NBATCH 4

// ---------------------------------------------------------------------------
// Scratch (static device globals — no allocation at runtime)
// ---------------------------------------------------------------------------
__device__ float g_h  [(size_t)MROWS * DMODEL];            // LN output (reused for LN2)
__device__ float g_q  [(size_t)MROWS * DMODEL];
__device__ float g_k  [(size_t)MROWS * DMODEL];
__device__ float g_v  [(size_t)MROWS * DMODEL];
__device__ float g_sc [(size_t)NBATCH * SEQ * SEQ];        // attention scores / probs
__device__ float g_att[(size_t)MROWS * DMODEL];            // attn @ V
__device__ float g_x1 [(size_t)MROWS * DMODEL];            // x + attn out
__device__ float g_mid[(size_t)MROWS * HDIM];              // FFN hidden

// ---------------------------------------------------------------------------
// LayerNorm: one block per row of 1024, 256 threads, 1 float4 per thread
// ---------------------------------------------------------------------------
__global__ void __launch_bounds__(256)
layernorm_kernel(const float* __restrict__ x, const float* __restrict__ gamma,
                 const float* __restrict__ beta, float* __restrict__ out)
{
    __shared__ float sm[64];
    const int row = blockIdx.x;
    const int t = threadIdx.x;
    const float4 v = ((const float4*)(x + (size_t)row * DMODEL))[t];

    float s  = v.x + v.y + v.z + v.w;
    float ss = v.x*v.x + v.y*v.y + v.z*v.z + v.w*v.w;
    #pragma unroll
    for (int o = 16; o > 0; o >>= 1) {
        s  += __shfl_down_sync(0xffffffffu, s,  o);
        ss += __shfl_down_sync(0xffffffffu, ss, o);
    }
    const int lane = t & 31, w = t >> 5;
    if (lane == 0) { sm[w] = s; sm[32 + w] = ss; }
    __syncthreads();
    if (t < 32) {
        s  = (t < 8) ? sm[t]      : 0.0f;
        ss = (t < 8) ? sm[32 + t] : 0.0f;
        #pragma unroll
        for (int o = 4; o > 0; o >>= 1) {
            s  += __shfl_down_sync(0xffffffffu, s,  o);
            ss += __shfl_down_sync(0xffffffffu, ss, o);
        }
        if (t == 0) { sm[0] = s; sm[32] = ss; }
    }
    __syncthreads();
    const float mu   = sm[0]  * (1.0f / DMODEL);
    const float var  = sm[32] * (1.0f / DMODEL) - mu * mu;
    const float rstd = rsqrtf(var + 1e-5f);

    const float4 g = ((const float4*)gamma)[t];
    const float4 b = ((const float4*)beta)[t];
    float4 o4;
    o4.x = (v.x - mu) * rstd * g.x + b.x;
    o4.y = (v.y - mu) * rstd * g.y + b.y;
    o4.z = (v.z - mu) * rstd * g.z + b.z;
    o4.w = (v.w - mu) * rstd * g.w + b.w;
    ((float4*)(out + (size_t)row * DMODEL))[t] = o4;
}

// ---------------------------------------------------------------------------
// Row softmax over 4096 elements, one block per row, 256 threads x 16 elems
// ---------------------------------------------------------------------------
__global__ void __launch_bounds__(256)
softmax_kernel(float* __restrict__ s)
{
    __shared__ float sm[8];
    const int row = blockIdx.x;
    const int t = threadIdx.x;
    float4* p = (float4*)(s + (size_t)row * SEQ);

    float4 v[4];
    float m = -3.402823e38f;
    #pragma unroll
    for (int i = 0; i < 4; i++) {
        v[i] = p[t + 256 * i];
        m = fmaxf(m, fmaxf(fmaxf(v[i].x, v[i].y), fmaxf(v[i].z, v[i].w)));
    }
    #pragma unroll
    for (int o = 16; o > 0; o >>= 1) m = fmaxf(m, __shfl_xor_sync(0xffffffffu, m, o));
    const int lane = t & 31, w = t >> 5;
    if (lane == 0) sm[w] = m;
    __syncthreads();
    float mb = sm[0];
    #pragma unroll
    for (int i = 1; i < 8; i++) mb = fmaxf(mb, sm[i]);
    __syncthreads();   // protect sm reuse below

    float sum = 0.0f;
    #pragma unroll
    for (int i = 0; i < 4; i++) {
        v[i].x = expf(v[i].x - mb); v[i].y = expf(v[i].y - mb);
        v[i].z = expf(v[i].z - mb); v[i].w = expf(v[i].w - mb);
        sum += v[i].x + v[i].y + v[i].z + v[i].w;
    }
    #pragma unroll
    for (int o = 16; o > 0; o >>= 1) sum += __shfl_xor_sync(0xffffffffu, sum, o);
    if (lane == 0) sm[w] = sum;
    __syncthreads();
    float tot = 0.0f;
    #pragma unroll
    for (int i = 0; i < 8; i++) tot += sm[i];
    const float inv = 1.0f / tot;

    #pragma unroll
    for (int i = 0; i < 4; i++) {
        v[i].x *= inv; v[i].y *= inv; v[i].z *= inv; v[i].w *= inv;
        p[t + 256 * i] = v[i];
    }
}

// ---------------------------------------------------------------------------
// SGEMM: C = alpha * A @ op(B) [+ bias] [GELU] [+ resid]
//   A: [M,K] row-major (optionally batched with stride sA)
//   B: NN -> [K,N] row-major; TB -> [N,K] row-major (B^T), batched via sB
//   128x128x8 tile, 8x8 per thread, 256 threads
// ---------------------------------------------------------------------------
template<bool TB, bool GELU, bool RESID>
__global__ void __launch_bounds__(256)
sgemm_kernel(const float* __restrict__ A, const float* __restrict__ Bm,
             const float* __restrict__ bias, const float* __restrict__ resid,
             float* __restrict__ C,
             int M, int N, int K,
             long long sA, long long sB, long long sC,
             float alpha)
{
    constexpr int BM = 128, BN = 128, BK = 8, TM = 8, TN = 8;
    __shared__ float As[BK][BM];
    __shared__ float Bs[BK][BN];

    const int z = blockIdx.z;
    A  += (long long)z * sA;
    Bm += (long long)z * sB;
    C  += (long long)z * sC;

    const int bx = blockIdx.x, by = blockIdx.y;
    const int tid = threadIdx.x;
    const int tx = tid & 15, ty = tid >> 4;

    const int lRow = tid >> 1;          // 0..127
    const int lCol = (tid & 1) * 4;     // 0 or 4
    const int bRow = tid >> 5;          // 0..7   (NN B load)
    const int bCol = (tid & 31) * 4;    // 0..124 (NN B load)

    const float* Ap = A + (long long)(by * BM + lRow) * K + lCol;
    const float* Bp = TB ? (Bm + (long long)(bx * BN + lRow) * K + lCol)
                         : (Bm + (long long)bRow * N + (long long)bx * BN + bCol);

    float acc[TM][TN];
    #pragma unroll
    for (int i = 0; i < TM; i++)
        #pragma unroll
        for (int j = 0; j < TN; j++) acc[i][j] = 0.0f;

    for (int k0 = 0; k0 < K; k0 += BK) {
        const float4 a = *(const float4*)(Ap + k0);
        As[lCol + 0][lRow] = a.x; As[lCol + 1][lRow] = a.y;
        As[lCol + 2][lRow] = a.z; As[lCol + 3][lRow] = a.w;
        if (TB) {
            const float4 b = *(const float4*)(Bp + k0);
            Bs[lCol + 0][lRow] = b.x; Bs[lCol + 1][lRow] = b.y;
            Bs[lCol + 2][lRow] = b.z; Bs[lCol + 3][lRow] = b.w;
        } else {
            const float4 b = *(const float4*)(Bp + (long long)k0 * N);
            *(float4*)&Bs[bRow][bCol] = b;
        }
        __syncthreads();

        #pragma unroll
        for (int kk = 0; kk < BK; kk++) {
            const float4 a0 = *(const float4*)&As[kk][ty * TM];
            const float4 a1 = *(const float4*)&As[kk][ty * TM + 4];
            const float4 b0 = *(const float4*)&Bs[kk][tx * TN];
            const float4 b1 = *(const float4*)&Bs[kk][tx * TN + 4];
            const float ra[8] = {a0.x, a0.y, a0.z, a0.w, a1.x, a1.y, a1.z, a1.w};
            const float rb[8] = {b0.x, b0.y, b0.z, b0.w, b1.x, b1.y, b1.z, b1.w};
            #pragma unroll
            for (int i = 0; i < TM; i++)
                #pragma unroll
                for (int j = 0; j < TN; j++)
                    acc[i][j] += ra[i] * rb[j];
        }
        __syncthreads();
    }

    const int row0 = by * BM + ty * TM;
    const int col0 = bx * BN + tx * TN;
    #pragma unroll
    for (int i = 0; i < TM; i++) {
        const long long off = (long long)(row0 + i) * N + col0;
        #pragma unroll
        for (int j = 0; j < TN; j++) {
            float vv = acc[i][j] * alpha;
            if (bias)  vv += bias[col0 + j];
            if (GELU)  vv = 0.5f * vv * (1.0f + erff(vv * 0.70710678118654752f));
            if (RESID) vv += resid[off + j];
            C[off + j] = vv;
        }
    }
}

// ---------------------------------------------------------------------------
// Launch: one transformer block
// ---------------------------------------------------------------------------
extern "C" void kernel_launch(void* const* d_in, const int* in_sizes, int n_in,
                              void* d_out, int out_size)
{
    const float* x   = (const float*)d_in[0];
    const float* wq  = (const float*)d_in[1];
    const float* bq  = (const float*)d_in[2];
    const float* wk  = (const float*)d_in[3];
    const float* bk  = (const float*)d_in[4];
    const float* wv  = (const float*)d_in[5];
    const float* bv  = (const float*)d_in[6];
    const float* wo  = (const float*)d_in[7];
    const float* bo  = (const float*)d_in[8];
    const float* w1  = (const float*)d_in[9];
    const float* b1  = (const float*)d_in[10];
    const float* w2  = (const float*)d_in[11];
    const float* b2  = (const float*)d_in[12];
    const float* g1  = (const float*)d_in[13];
    const float* be1 = (const float*)d_in[14];
    const float* g2  = (const float*)d_in[15];
    const float* be2 = (const float*)d_in[16];
    float* out = (float*)d_out;

    float *h, *q, *k, *v, *sc, *att, *x1, *mid;
    cudaGetSymbolAddress((void**)&h,   g_h);
    cudaGetSymbolAddress((void**)&q,   g_q);
    cudaGetSymbolAddress((void**)&k,   g_k);
    cudaGetSymbolAddress((void**)&v,   g_v);
    cudaGetSymbolAddress((void**)&sc,  g_sc);
    cudaGetSymbolAddress((void**)&att, g_att);
    cudaGetSymbolAddress((void**)&x1,  g_x1);
    cudaGetSymbolAddress((void**)&mid, g_mid);

    const long long sdQ = (long long)SEQ * DMODEL;   // per-batch q/k/v stride
    const long long sdS = (long long)SEQ * SEQ;      // per-batch score stride

    // ---- attention sub-block ----
    layernorm_kernel<<<MROWS, 256>>>(x, g1, be1, h);

    dim3 gD(DMODEL / 128, MROWS / 128, 1);
    sgemm_kernel<false, false, false><<<gD, 256>>>(h, wq, bq, nullptr, q,
        MROWS, DMODEL, DMODEL, 0, 0, 0, 1.0f);
    sgemm_kernel<false, false, false><<<gD, 256>>>(h, wk, bk, nullptr, k,
        MROWS, DMODEL, DMODEL, 0, 0, 0, 1.0f);
    sgemm_kernel<false, false, false><<<gD, 256>>>(h, wv, bv, nullptr, v,
        MROWS, DMODEL, DMODEL, 0, 0, 0, 1.0f);

    // scores = (Q @ K^T) / sqrt(D), batched over B
    dim3 gS(SEQ / 128, SEQ / 128, NBATCH);
    sgemm_kernel<true, false, false><<<gS, 256>>>(q, k, nullptr, nullptr, sc,
        SEQ, SEQ, DMODEL, sdQ, sdQ, sdS, 0.03125f);

    softmax_kernel<<<MROWS, 256>>>(sc);

    // attn @ V, batched over B
    dim3 gAV(DMODEL / 128, SEQ / 128, NBATCH);
    sgemm_kernel<false, false, false><<<gAV, 256>>>(sc, v, nullptr, nullptr, att,
        SEQ, DMODEL, SEQ, sdS, sdQ, sdQ, 1.0f);

    // x1 = x + attn_out @ Wo + bo
    sgemm_kernel<false, false, true><<<gD, 256>>>(att, wo, bo, x, x1,
        MROWS, DMODEL, DMODEL, 0, 0, 0, 1.0f);

    // ---- FFN sub-block ----
    layernorm_kernel<<<MROWS, 256>>>(x1, g2, be2, h);

    dim3 gF1(HDIM / 128, MROWS / 128, 1);
    sgemm_kernel<false, true, false><<<gF1, 256>>>(h, w1, b1, nullptr, mid,
        MROWS, HDIM, DMODEL, 0, 0, 0, 1.0f);

    // out = x1 + GELU(h@w1+b1) @ w2 + b2
    sgemm_kernel<false, false, true><<<gD, 256>>>(mid, w2, b2, x1, out,
        MROWS, DMODEL, HDIM, 0, 0, 0, 1.0f);
}

// round 14
// speedup vs baseline: 1.0014x; 1.0014x over previous
#include <cuda_runtime.h>
#include <math.h>

// ---------------------------------------------------------------------------
// Problem constants (B=4, S=4096, D=1024, H=4096)
// ---------------------------------------------------------------------------
#define MROWS 16384          // B*S
#define DMODEL 1024
#define HDIM   4096
#define SEQ    4096
#define NBATCH 4

// ---------------------------------------------------------------------------
// Scratch (static device globals — no allocation at runtime)
// ---------------------------------------------------------------------------
__device__ float g_h  [(size_t)MROWS * DMODEL];            // LN output (reused for LN2)
__device__ float g_q  [(size_t)MROWS * DMODEL];
__device__ float g_k  [(size_t)MROWS * DMODEL];
__device__ float g_v  [(size_t)MROWS * DMODEL];
__device__ float g_sc [(size_t)NBATCH * SEQ * SEQ];        // attention scores / probs
__device__ float g_att[(size_t)MROWS * DMODEL];            // attn @ V
__device__ float g_x1 [(size_t)MROWS * DMODEL];            // x + attn out
__device__ float g_mid[(size_t)MROWS * HDIM];              // FFN hidden

// ---------------------------------------------------------------------------
// LayerNorm: one block per row of 1024, 256 threads, 1 float4 per thread
// ---------------------------------------------------------------------------
__global__ void __launch_bounds__(256)
layernorm_kernel(const float* __restrict__ x, const float* __restrict__ gamma,
                 const float* __restrict__ beta, float* __restrict__ out)
{
    __shared__ float sm[64];
    const int row = blockIdx.x;
    const int t = threadIdx.x;
    const float4 v = ((const float4*)(x + (size_t)row * DMODEL))[t];

    float s  = v.x + v.y + v.z + v.w;
    float ss = v.x*v.x + v.y*v.y + v.z*v.z + v.w*v.w;
    #pragma unroll
    for (int o = 16; o > 0; o >>= 1) {
        s  += __shfl_down_sync(0xffffffffu, s,  o);
        ss += __shfl_down_sync(0xffffffffu, ss, o);
    }
    const int lane = t & 31, w = t >> 5;
    if (lane == 0) { sm[w] = s; sm[32 + w] = ss; }
    __syncthreads();
    if (t < 32) {
        s  = (t < 8) ? sm[t]      : 0.0f;
        ss = (t < 8) ? sm[32 + t] : 0.0f;
        #pragma unroll
        for (int o = 4; o > 0; o >>= 1) {
            s  += __shfl_down_sync(0xffffffffu, s,  o);
            ss += __shfl_down_sync(0xffffffffu, ss, o);
        }
        if (t == 0) { sm[0] = s; sm[32] = ss; }
    }
    __syncthreads();
    const float mu   = sm[0]  * (1.0f / DMODEL);
    const float var  = sm[32] * (1.0f / DMODEL) - mu * mu;
    const float rstd = rsqrtf(var + 1e-5f);

    const float4 g = ((const float4*)gamma)[t];
    const float4 b = ((const float4*)beta)[t];
    float4 o4;
    o4.x = (v.x - mu) * rstd * g.x + b.x;
    o4.y = (v.y - mu) * rstd * g.y + b.y;
    o4.z = (v.z - mu) * rstd * g.z + b.z;
    o4.w = (v.w - mu) * rstd * g.w + b.w;
    ((float4*)(out + (size_t)row * DMODEL))[t] = o4;
}

// ---------------------------------------------------------------------------
// Row softmax over 4096 elements, one block per row, 256 threads x 16 elems
// ---------------------------------------------------------------------------
__global__ void __launch_bounds__(256)
softmax_kernel(float* __restrict__ s)
{
    __shared__ float sm[8];
    const int row = blockIdx.x;
    const int t = threadIdx.x;
    float4* p = (float4*)(s + (size_t)row * SEQ);

    float4 v[4];
    float m = -3.402823e38f;
    #pragma unroll
    for (int i = 0; i < 4; i++) {
        v[i] = p[t + 256 * i];
        m = fmaxf(m, fmaxf(fmaxf(v[i].x, v[i].y), fmaxf(v[i].z, v[i].w)));
    }
    #pragma unroll
    for (int o = 16; o > 0; o >>= 1) m = fmaxf(m, __shfl_xor_sync(0xffffffffu, m, o));
    const int lane = t & 31, w = t >> 5;
    if (lane == 0) sm[w] = m;
    __syncthreads();
    float mb = sm[0];
    #pragma unroll
    for (int i = 1; i < 8; i++) mb = fmaxf(mb, sm[i]);
    __syncthreads();   // protect sm reuse below

    float sum = 0.0f;
    #pragma unroll
    for (int i = 0; i < 4; i++) {
        v[i].x = expf(v[i].x - mb); v[i].y = expf(v[i].y - mb);
        v[i].z = expf(v[i].z - mb); v[i].w = expf(v[i].w - mb);
        sum += v[i].x + v[i].y + v[i].z + v[i].w;
    }
    #pragma unroll
    for (int o = 16; o > 0; o >>= 1) sum += __shfl_xor_sync(0xffffffffu, sum, o);
    if (lane == 0) sm[w] = sum;
    __syncthreads();
    float tot = 0.0f;
    #pragma unroll
    for (int i = 0; i < 8; i++) tot += sm[i];
    const float inv = 1.0f / tot;

    #pragma unroll
    for (int i = 0; i < 4; i++) {
        v[i].x *= inv; v[i].y *= inv; v[i].z *= inv; v[i].w *= inv;
        p[t + 256 * i] = v[i];
    }
}

// ---------------------------------------------------------------------------
// SGEMM: C = alpha * A @ op(B) [+ bias] [GELU] [+ resid]
//   A: [M,K] row-major (optionally batched with stride sA)
//   B: NN -> [K,N] row-major; TB -> [N,K] row-major (B^T), batched via sB
//   128x128x8 tile, 8x8 per thread, 256 threads
// ---------------------------------------------------------------------------
template<bool TB, bool GELU, bool RESID>
__global__ void __launch_bounds__(256)
sgemm_kernel(const float* __restrict__ A, const float* __restrict__ Bm,
             const float* __restrict__ bias, const float* __restrict__ resid,
             float* __restrict__ C,
             int M, int N, int K,
             long long sA, long long sB, long long sC,
             float alpha)
{
    constexpr int BM = 128, BN = 128, BK = 8, TM = 8, TN = 8;
    __shared__ float As[BK][BM];
    __shared__ float Bs[BK][BN];

    const int z = blockIdx.z;
    A  += (long long)z * sA;
    Bm += (long long)z * sB;
    C  += (long long)z * sC;

    const int bx = blockIdx.x, by = blockIdx.y;
    const int tid = threadIdx.x;
    const int tx = tid & 15, ty = tid >> 4;

    const int lRow = tid >> 1;          // 0..127
    const int lCol = (tid & 1) * 4;     // 0 or 4
    const int bRow = tid >> 5;          // 0..7   (NN B load)
    const int bCol = (tid & 31) * 4;    // 0..124 (NN B load)

    const float* Ap = A + (long long)(by * BM + lRow) * K + lCol;
    const float* Bp = TB ? (Bm + (long long)(bx * BN + lRow) * K + lCol)
                         : (Bm + (long long)bRow * N + (long long)bx * BN + bCol);

    float acc[TM][TN];
    #pragma unroll
    for (int i = 0; i < TM; i++)
        #pragma unroll
        for (int j = 0; j < TN; j++) acc[i][j] = 0.0f;

    for (int k0 = 0; k0 < K; k0 += BK) {
        const float4 a = *(const float4*)(Ap + k0);
        As[lCol + 0][lRow] = a.x; As[lCol + 1][lRow] = a.y;
        As[lCol + 2][lRow] = a.z; As[lCol + 3][lRow] = a.w;
        if (TB) {
            const float4 b = *(const float4*)(Bp + k0);
            Bs[lCol + 0][lRow] = b.x; Bs[lCol + 1][lRow] = b.y;
            Bs[lCol + 2][lRow] = b.z; Bs[lCol + 3][lRow] = b.w;
        } else {
            const float4 b = *(const float4*)(Bp + (long long)k0 * N);
            *(float4*)&Bs[bRow][bCol] = b;
        }
        __syncthreads();

        #pragma unroll
        for (int kk = 0; kk < BK; kk++) {
            const float4 a0 = *(const float4*)&As[kk][ty * TM];
            const float4 a1 = *(const float4*)&As[kk][ty * TM + 4];
            const float4 b0 = *(const float4*)&Bs[kk][tx * TN];
            const float4 b1 = *(const float4*)&Bs[kk][tx * TN + 4];
            const float ra[8] = {a0.x, a0.y, a0.z, a0.w, a1.x, a1.y, a1.z, a1.w};
            const float rb[8] = {b0.x, b0.y, b0.z, b0.w, b1.x, b1.y, b1.z, b1.w};
            #pragma unroll
            for (int i = 0; i < TM; i++)
                #pragma unroll
                for (int j = 0; j < TN; j++)
                    acc[i][j] += ra[i] * rb[j];
        }
        __syncthreads();
    }

    const int row0 = by * BM + ty * TM;
    const int col0 = bx * BN + tx * TN;
    #pragma unroll
    for (int i = 0; i < TM; i++) {
        const long long off = (long long)(row0 + i) * N + col0;
        #pragma unroll
        for (int j = 0; j < TN; j++) {
            float vv = acc[i][j] * alpha;
            if (bias)  vv += bias[col0 + j];
            if (GELU)  vv = 0.5f * vv * (1.0f + erff(vv * 0.70710678118654752f));
            if (RESID) vv += resid[off + j];
            C[off + j] = vv;
        }
    }
}

// ---------------------------------------------------------------------------
// Launch: one transformer block
// ---------------------------------------------------------------------------
extern "C" void kernel_launch(void* const* d_in, const int* in_sizes, int n_in,
                              void* d_out, int out_size)
{
    const float* x   = (const float*)d_in[0];
    const float* wq  = (const float*)d_in[1];
    const float* bq  = (const float*)d_in[2];
    const float* wk  = (const float*)d_in[3];
    const float* bk  = (const float*)d_in[4];
    const float* wv  = (const float*)d_in[5];
    const float* bv  = (const float*)d_in[6];
    const float* wo  = (const float*)d_in[7];
    const float* bo  = (const float*)d_in[8];
    const float* w1  = (const float*)d_in[9];
    const float* b1  = (const float*)d_in[10];
    const float* w2  = (const float*)d_in[11];
    const float* b2  = (const float*)d_in[12];
    const float* g1  = (const float*)d_in[13];
    const float* be1 = (const float*)d_in[14];
    const float* g2  = (const float*)d_in[15];
    const float* be2 = (const float*)d_in[16];
    float* out = (float*)d_out;

    float *h, *q, *k, *v, *sc, *att, *x1, *mid;
    cudaGetSymbolAddress((void**)&h,   g_h);
    cudaGetSymbolAddress((void**)&q,   g_q);
    cudaGetSymbolAddress((void**)&k,   g_k);
    cudaGetSymbolAddress((void**)&v,   g_v);
    cudaGetSymbolAddress((void**)&sc,  g_sc);
    cudaGetSymbolAddress((void**)&att, g_att);
    cudaGetSymbolAddress((void**)&x1,  g_x1);
    cudaGetSymbolAddress((void**)&mid, g_mid);

    const long long sdQ = (long long)SEQ * DMODEL;   // per-batch q/k/v stride
    const long long sdS = (long long)SEQ * SEQ;      // per-batch score stride

    // ---- attention sub-block ----
    layernorm_kernel<<<MROWS, 256>>>(x, g1, be1, h);

    dim3 gD(DMODEL / 128, MROWS / 128, 1);
    sgemm_kernel<false, false, false><<<gD, 256>>>(h, wq, bq, nullptr, q,
        MROWS, DMODEL, DMODEL, 0, 0, 0, 1.0f);
    sgemm_kernel<false, false, false><<<gD, 256>>>(h, wk, bk, nullptr, k,
        MROWS, DMODEL, DMODEL, 0, 0, 0, 1.0f);
    sgemm_kernel<false, false, false><<<gD, 256>>>(h, wv, bv, nullptr, v,
        MROWS, DMODEL, DMODEL, 0, 0, 0, 1.0f);

    // scores = (Q @ K^T) / sqrt(D), batched over B
    dim3 gS(SEQ / 128, SEQ / 128, NBATCH);
    sgemm_kernel<true, false, false><<<gS, 256>>>(q, k, nullptr, nullptr, sc,
        SEQ, SEQ, DMODEL, sdQ, sdQ, sdS, 0.03125f);

    softmax_kernel<<<MROWS, 256>>>(sc);

    // attn @ V, batched over B
    dim3 gAV(DMODEL / 128, SEQ / 128, NBATCH);
    sgemm_kernel<false, false, false><<<gAV, 256>>>(sc, v, nullptr, nullptr, att,
        SEQ, DMODEL, SEQ, sdS, sdQ, sdQ, 1.0f);

    // x1 = x + attn_out @ Wo + bo
    sgemm_kernel<false, false, true><<<gD, 256>>>(att, wo, bo, x, x1,
        MROWS, DMODEL, DMODEL, 0, 0, 0, 1.0f);

    // ---- FFN sub-block ----
    layernorm_kernel<<<MROWS, 256>>>(x1, g2, be2, h);

    dim3 gF1(HDIM / 128, MROWS / 128, 1);
    sgemm_kernel<false, true, false><<<gF1, 256>>>(h, w1, b1, nullptr, mid,
        MROWS, HDIM, DMODEL, 0, 0, 0, 1.0f);

    // out = x1 + GELU(h@w1+b1) @ w2 + b2
    sgemm_kernel<false, false, true><<<gD, 256>>>(mid, w2, b2, x1, out,
        MROWS, DMODEL, HDIM, 0, 0, 0, 1.0f);
}

// round 15
// speedup vs baseline: 3.5235x; 3.5185x over previous
#include <cuda_runtime.h>
#include <math.h>

// ---------------------------------------------------------------------------
// Problem constants (B=4, S=4096, D=1024, H=4096)
// ---------------------------------------------------------------------------
#define MROWS 16384          // B*S
#define DMODEL 1024
#define HDIM   4096
#define SEQ    4096
#define NBATCH 4

// ---------------------------------------------------------------------------
// Scratch (static device globals — no allocation at runtime)
// ---------------------------------------------------------------------------
__device__ float g_h  [(size_t)MROWS * DMODEL];
__device__ float g_q  [(size_t)MROWS * DMODEL];
__device__ float g_k  [(size_t)MROWS * DMODEL];
__device__ float g_v  [(size_t)MROWS * DMODEL];
__device__ float g_sc [(size_t)NBATCH * SEQ * SEQ];
__device__ float g_att[(size_t)MROWS * DMODEL];
__device__ float g_x1 [(size_t)MROWS * DMODEL];
__device__ float g_mid[(size_t)MROWS * HDIM];

// ---------------------------------------------------------------------------
// Helpers: tf32 convert (round-to-nearest — avoids truncation bias), cp.async
// ---------------------------------------------------------------------------
__device__ __forceinline__ unsigned cvt_tf32(float f) {
    unsigned r;
    asm("cvt.rna.tf32.f32 %0, %1;" : "=r"(r) : "f"(f));
    return r;
}

__device__ __forceinline__ void cpa16(float* dst_smem, const float* src_gmem) {
    unsigned s = (unsigned)__cvta_generic_to_shared(dst_smem);
    asm volatile("cp.async.cg.shared.global [%0], [%1], 16;\n" :: "r"(s), "l"(src_gmem));
}
#define CP_COMMIT() asm volatile("cp.async.commit_group;\n" ::: "memory")
#define CP_WAIT(n)  asm volatile("cp.async.wait_group %0;\n" :: "n"(n) : "memory")

__device__ __forceinline__ void mma_tf32(float c[4], const unsigned a[4], const unsigned b[2]) {
    asm volatile(
        "mma.sync.aligned.m16n8k8.row.col.f32.tf32.tf32.f32 "
        "{%0,%1,%2,%3},{%4,%5,%6,%7},{%8,%9},{%0,%1,%2,%3};\n"
        : "+f"(c[0]), "+f"(c[1]), "+f"(c[2]), "+f"(c[3])
        : "r"(a[0]), "r"(a[1]), "r"(a[2]), "r"(a[3]), "r"(b[0]), "r"(b[1]));
}

// ---------------------------------------------------------------------------
// LayerNorm: one block per row of 1024
// ---------------------------------------------------------------------------
__global__ void __launch_bounds__(256)
layernorm_kernel(const float* __restrict__ x, const float* __restrict__ gamma,
                 const float* __restrict__ beta, float* __restrict__ out)
{
    __shared__ float sm[64];
    const int row = blockIdx.x;
    const int t = threadIdx.x;
    const float4 v = ((const float4*)(x + (size_t)row * DMODEL))[t];

    float s  = v.x + v.y + v.z + v.w;
    float ss = v.x*v.x + v.y*v.y + v.z*v.z + v.w*v.w;
    #pragma unroll
    for (int o = 16; o > 0; o >>= 1) {
        s  += __shfl_down_sync(0xffffffffu, s,  o);
        ss += __shfl_down_sync(0xffffffffu, ss, o);
    }
    const int lane = t & 31, w = t >> 5;
    if (lane == 0) { sm[w] = s; sm[32 + w] = ss; }
    __syncthreads();
    if (t < 32) {
        s  = (t < 8) ? sm[t]      : 0.0f;
        ss = (t < 8) ? sm[32 + t] : 0.0f;
        #pragma unroll
        for (int o = 4; o > 0; o >>= 1) {
            s  += __shfl_down_sync(0xffffffffu, s,  o);
            ss += __shfl_down_sync(0xffffffffu, ss, o);
        }
        if (t == 0) { sm[0] = s; sm[32] = ss; }
    }
    __syncthreads();
    const float mu   = sm[0]  * (1.0f / DMODEL);
    const float var  = sm[32] * (1.0f / DMODEL) - mu * mu;
    const float rstd = rsqrtf(var + 1e-5f);

    const float4 g = ((const float4*)gamma)[t];
    const float4 b = ((const float4*)beta)[t];
    float4 o4;
    o4.x = (v.x - mu) * rstd * g.x + b.x;
    o4.y = (v.y - mu) * rstd * g.y + b.y;
    o4.z = (v.z - mu) * rstd * g.z + b.z;
    o4.w = (v.w - mu) * rstd * g.w + b.w;
    ((float4*)(out + (size_t)row * DMODEL))[t] = o4;
}

// ---------------------------------------------------------------------------
// Row softmax over 4096 elements
// ---------------------------------------------------------------------------
__global__ void __launch_bounds__(256)
softmax_kernel(float* __restrict__ s)
{
    __shared__ float sm[8];
    const int row = blockIdx.x;
    const int t = threadIdx.x;
    float4* p = (float4*)(s + (size_t)row * SEQ);

    float4 v[4];
    float m = -3.402823e38f;
    #pragma unroll
    for (int i = 0; i < 4; i++) {
        v[i] = p[t + 256 * i];
        m = fmaxf(m, fmaxf(fmaxf(v[i].x, v[i].y), fmaxf(v[i].z, v[i].w)));
    }
    #pragma unroll
    for (int o = 16; o > 0; o >>= 1) m = fmaxf(m, __shfl_xor_sync(0xffffffffu, m, o));
    const int lane = t & 31, w = t >> 5;
    if (lane == 0) sm[w] = m;
    __syncthreads();
    float mb = sm[0];
    #pragma unroll
    for (int i = 1; i < 8; i++) mb = fmaxf(mb, sm[i]);
    __syncthreads();

    float sum = 0.0f;
    #pragma unroll
    for (int i = 0; i < 4; i++) {
        v[i].x = expf(v[i].x - mb); v[i].y = expf(v[i].y - mb);
        v[i].z = expf(v[i].z - mb); v[i].w = expf(v[i].w - mb);
        sum += v[i].x + v[i].y + v[i].z + v[i].w;
    }
    #pragma unroll
    for (int o = 16; o > 0; o >>= 1) sum += __shfl_xor_sync(0xffffffffu, sum, o);
    if (lane == 0) sm[w] = sum;
    __syncthreads();
    float tot = 0.0f;
    #pragma unroll
    for (int i = 0; i < 8; i++) tot += sm[i];
    const float inv = 1.0f / tot;

    #pragma unroll
    for (int i = 0; i < 4; i++) {
        v[i].x *= inv; v[i].y *= inv; v[i].z *= inv; v[i].w *= inv;
        p[t + 256 * i] = v[i];
    }
}

// ---------------------------------------------------------------------------
// tf32 tensor-core GEMM: C = alpha * A @ op(B) [+bias][GELU][+resid]
//   A [M,K] row-major.  NN: B [K,N] row-major.  TB: B stored [N,K] row-major.
//   128x128 block tile, BK=16, 8 warps (64x32 warp tile), m16n8k8 tf32 MMA,
//   cp.async double-buffered smem, conflict-free padded strides.
// ---------------------------------------------------------------------------
template<bool TB, bool GELU, bool RESID>
__global__ void __launch_bounds__(256, 2)
gemm_tf32(const float* __restrict__ A, const float* __restrict__ Bm,
          const float* __restrict__ bias, const float* __restrict__ resid,
          float* __restrict__ C,
          int M, int N, int K,
          long long sA, long long sB, long long sC,
          float alpha)
{
    constexpr int BK = 16;
    constexpr int AST = 20;                 // As row stride (pad 16->20, conflict-free)
    constexpr int BST = TB ? 20 : 136;      // Bs stride
    constexpr int BS_ELEMS = TB ? (128 * 20) : (BK * 136);

    __shared__ float As[2][128 * AST];
    __shared__ float Bs[2][BS_ELEMS];

    const int z = blockIdx.z;
    A  += (long long)z * sA;
    Bm += (long long)z * sB;
    C  += (long long)z * sC;

    const int bx = blockIdx.x, by = blockIdx.y;
    const int tid = threadIdx.x;
    const int lane = tid & 31;
    const int warp = tid >> 5;
    const int gid = lane >> 2;       // 0..7
    const int tig = lane & 3;        // 0..3
    const int wm0 = (warp & 1) * 64; // warp row origin in block tile
    const int wn0 = (warp >> 1) * 32;

    // gmem load coordinates (A-tile: 128 rows x 4 float4; each thread 2 float4)
    const int ar[2]  = { (tid + 0)   >> 2, (tid + 256) >> 2 };
    const int ac4[2] = { (tid + 0)   & 3,  (tid + 256) & 3  };

    float acc[4][4][4];
    #pragma unroll
    for (int i = 0; i < 4; i++)
        #pragma unroll
        for (int j = 0; j < 4; j++)
            #pragma unroll
            for (int r = 0; r < 4; r++) acc[i][j][r] = 0.0f;

    const int NT = K / BK;

    // ---- tile loader (cp.async, raw fp32) ----
    auto load_tile = [&](int t, int buf) {
        const int k0 = t * BK;
        #pragma unroll
        for (int i = 0; i < 2; i++) {
            cpa16(&As[buf][ar[i] * AST + ac4[i] * 4],
                  A + (long long)(by * 128 + ar[i]) * K + k0 + ac4[i] * 4);
        }
        if (TB) {
            #pragma unroll
            for (int i = 0; i < 2; i++) {
                cpa16(&Bs[buf][ar[i] * BST + ac4[i] * 4],
                      Bm + (long long)(bx * 128 + ar[i]) * K + k0 + ac4[i] * 4);
            }
        } else {
            #pragma unroll
            for (int i = 0; i < 2; i++) {
                const int f  = tid + 256 * i;
                const int r  = f >> 5;        // 0..15
                const int c4 = f & 31;        // 0..31
                cpa16(&Bs[buf][r * BST + c4 * 4],
                      Bm + (long long)(k0 + r) * N + bx * 128 + c4 * 4);
            }
        }
        CP_COMMIT();
    };

    load_tile(0, 0);

    for (int t = 0; t < NT; ++t) {
        if (t + 1 < NT) {
            load_tile(t + 1, (t + 1) & 1);
            CP_WAIT(1);
        } else {
            CP_WAIT(0);
        }
        __syncthreads();

        const float* Ab = As[t & 1];
        const float* Bb = Bs[t & 1];

        #pragma unroll
        for (int kk = 0; kk < 2; ++kk) {
            const int kb = kk * 8;
            unsigned af[4][4], bf[4][2];
            #pragma unroll
            for (int i = 0; i < 4; i++) {
                const float* p = Ab + (wm0 + i * 16 + gid) * AST + kb + tig;
                af[i][0] = cvt_tf32(p[0]);
                af[i][1] = cvt_tf32(p[8 * AST]);
                af[i][2] = cvt_tf32(p[4]);
                af[i][3] = cvt_tf32(p[8 * AST + 4]);
            }
            #pragma unroll
            for (int j = 0; j < 4; j++) {
                if (TB) {
                    const float* p = Bb + (wn0 + j * 8 + gid) * BST + kb + tig;
                    bf[j][0] = cvt_tf32(p[0]);
                    bf[j][1] = cvt_tf32(p[4]);
                } else {
                    const float* p = Bb + (kb + tig) * BST + wn0 + j * 8 + gid;
                    bf[j][0] = cvt_tf32(p[0]);
                    bf[j][1] = cvt_tf32(p[4 * BST]);
                }
            }
            #pragma unroll
            for (int i = 0; i < 4; i++)
                #pragma unroll
                for (int j = 0; j < 4; j++)
                    mma_tf32(acc[i][j], af[i], bf[j]);
        }
        __syncthreads();
    }

    // ---- epilogue ----
    #pragma unroll
    for (int i = 0; i < 4; i++) {
        const int row0 = by * 128 + wm0 + i * 16 + gid;
        #pragma unroll
        for (int j = 0; j < 4; j++) {
            const int col = bx * 128 + wn0 + j * 8 + tig * 2;
            float b0 = 0.0f, b1 = 0.0f;
            if (bias) { b0 = bias[col]; b1 = bias[col + 1]; }
            #pragma unroll
            for (int h = 0; h < 2; h++) {          // h=0: rows row0, h=1: row0+8
                const int row = row0 + h * 8;
                float v0 = acc[i][j][h * 2 + 0] * alpha + b0;
                float v1 = acc[i][j][h * 2 + 1] * alpha + b1;
                if (GELU) {
                    v0 = 0.5f * v0 * (1.0f + erff(v0 * 0.70710678118654752f));
                    v1 = 0.5f * v1 * (1.0f + erff(v1 * 0.70710678118654752f));
                }
                const long long off = (long long)row * N + col;
                if (RESID) { v0 += resid[off]; v1 += resid[off + 1]; }
                *(float2*)(C + off) = make_float2(v0, v1);
            }
        }
    }
}

// ---------------------------------------------------------------------------
// Launch: one transformer block
// ---------------------------------------------------------------------------
extern "C" void kernel_launch(void* const* d_in, const int* in_sizes, int n_in,
                              void* d_out, int out_size)
{
    const float* x   = (const float*)d_in[0];
    const float* wq  = (const float*)d_in[1];
    const float* bq  = (const float*)d_in[2];
    const float* wk  = (const float*)d_in[3];
    const float* bk  = (const float*)d_in[4];
    const float* wv  = (const float*)d_in[5];
    const float* bv  = (const float*)d_in[6];
    const float* wo  = (const float*)d_in[7];
    const float* bo  = (const float*)d_in[8];
    const float* w1  = (const float*)d_in[9];
    const float* b1  = (const float*)d_in[10];
    const float* w2  = (const float*)d_in[11];
    const float* b2  = (const float*)d_in[12];
    const float* g1  = (const float*)d_in[13];
    const float* be1 = (const float*)d_in[14];
    const float* g2  = (const float*)d_in[15];
    const float* be2 = (const float*)d_in[16];
    float* out = (float*)d_out;

    float *h, *q, *k, *v, *sc, *att, *x1, *mid;
    cudaGetSymbolAddress((void**)&h,   g_h);
    cudaGetSymbolAddress((void**)&q,   g_q);
    cudaGetSymbolAddress((void**)&k,   g_k);
    cudaGetSymbolAddress((void**)&v,   g_v);
    cudaGetSymbolAddress((void**)&sc,  g_sc);
    cudaGetSymbolAddress((void**)&att, g_att);
    cudaGetSymbolAddress((void**)&x1,  g_x1);
    cudaGetSymbolAddress((void**)&mid, g_mid);

    const long long sdQ = (long long)SEQ * DMODEL;
    const long long sdS = (long long)SEQ * SEQ;

    // ---- attention sub-block ----
    layernorm_kernel<<<MROWS, 256>>>(x, g1, be1, h);

    dim3 gD(DMODEL / 128, MROWS / 128, 1);
    gemm_tf32<false, false, false><<<gD, 256>>>(h, wq, bq, nullptr, q,
        MROWS, DMODEL, DMODEL, 0, 0, 0, 1.0f);
    gemm_tf32<false, false, false><<<gD, 256>>>(h, wk, bk, nullptr, k,
        MROWS, DMODEL, DMODEL, 0, 0, 0, 1.0f);
    gemm_tf32<false, false, false><<<gD, 256>>>(h, wv, bv, nullptr, v,
        MROWS, DMODEL, DMODEL, 0, 0, 0, 1.0f);

    // scores = (Q @ K^T) / sqrt(D), batched over B
    dim3 gS(SEQ / 128, SEQ / 128, NBATCH);
    gemm_tf32<true, false, false><<<gS, 256>>>(q, k, nullptr, nullptr, sc,
        SEQ, SEQ, DMODEL, sdQ, sdQ, sdS, 0.03125f);

    softmax_kernel<<<MROWS, 256>>>(sc);

    // attn @ V, batched over B
    dim3 gAV(DMODEL / 128, SEQ / 128, NBATCH);
    gemm_tf32<false, false, false><<<gAV, 256>>>(sc, v, nullptr, nullptr, att,
        SEQ, DMODEL, SEQ, sdS, sdQ, sdQ, 1.0f);

    // x1 = x + attn_out @ Wo + bo
    gemm_tf32<false, false, true><<<gD, 256>>>(att, wo, bo, x, x1,
        MROWS, DMODEL, DMODEL, 0, 0, 0, 1.0f);

    // ---- FFN sub-block ----
    layernorm_kernel<<<MROWS, 256>>>(x1, g2, be2, h);

    dim3 gF1(HDIM / 128, MROWS / 128, 1);
    gemm_tf32<false, true, false><<<gF1, 256>>>(h, w1, b1, nullptr, mid,
        MROWS, HDIM, DMODEL, 0, 0, 0, 1.0f);

    // out = x1 + GELU(h@w1+b1) @ w2 + b2
    gemm_tf32<false, false, true><<<gD, 256>>>(mid, w2, b2, x1, out,
        MROWS, DMODEL, HDIM, 0, 0, 0, 1.0f);
}

// round 16
// speedup vs baseline: 3.5239x; 1.0001x over previous
#include <cuda_runtime.h>
#include <math.h>

// ---------------------------------------------------------------------------
// Problem constants (B=4, S=4096, D=1024, H=4096)
// ---------------------------------------------------------------------------
#define MROWS 16384          // B*S
#define DMODEL 1024
#define HDIM   4096
#define SEQ    4096
#define NBATCH 4

// ---------------------------------------------------------------------------
// Scratch (static device globals — no allocation at runtime)
// ---------------------------------------------------------------------------
__device__ float g_h  [(size_t)MROWS * DMODEL];
__device__ float g_q  [(size_t)MROWS * DMODEL];
__device__ float g_k  [(size_t)MROWS * DMODEL];
__device__ float g_v  [(size_t)MROWS * DMODEL];
__device__ float g_sc [(size_t)NBATCH * SEQ * SEQ];
__device__ float g_att[(size_t)MROWS * DMODEL];
__device__ float g_x1 [(size_t)MROWS * DMODEL];
__device__ float g_mid[(size_t)MROWS * HDIM];

// ---------------------------------------------------------------------------
// Helpers: tf32 convert (round-to-nearest — avoids truncation bias), cp.async
// ---------------------------------------------------------------------------
__device__ __forceinline__ unsigned cvt_tf32(float f) {
    unsigned r;
    asm("cvt.rna.tf32.f32 %0, %1;" : "=r"(r) : "f"(f));
    return r;
}

__device__ __forceinline__ void cpa16(float* dst_smem, const float* src_gmem) {
    unsigned s = (unsigned)__cvta_generic_to_shared(dst_smem);
    asm volatile("cp.async.cg.shared.global [%0], [%1], 16;\n" :: "r"(s), "l"(src_gmem));
}
#define CP_COMMIT() asm volatile("cp.async.commit_group;\n" ::: "memory")
#define CP_WAIT(n)  asm volatile("cp.async.wait_group %0;\n" :: "n"(n) : "memory")

__device__ __forceinline__ void mma_tf32(float c[4], const unsigned a[4], const unsigned b[2]) {
    asm volatile(
        "mma.sync.aligned.m16n8k8.row.col.f32.tf32.tf32.f32 "
        "{%0,%1,%2,%3},{%4,%5,%6,%7},{%8,%9},{%0,%1,%2,%3};\n"
        : "+f"(c[0]), "+f"(c[1]), "+f"(c[2]), "+f"(c[3])
        : "r"(a[0]), "r"(a[1]), "r"(a[2]), "r"(a[3]), "r"(b[0]), "r"(b[1]));
}

// ---------------------------------------------------------------------------
// LayerNorm: one block per row of 1024
// ---------------------------------------------------------------------------
__global__ void __launch_bounds__(256)
layernorm_kernel(const float* __restrict__ x, const float* __restrict__ gamma,
                 const float* __restrict__ beta, float* __restrict__ out)
{
    __shared__ float sm[64];
    const int row = blockIdx.x;
    const int t = threadIdx.x;
    const float4 v = ((const float4*)(x + (size_t)row * DMODEL))[t];

    float s  = v.x + v.y + v.z + v.w;
    float ss = v.x*v.x + v.y*v.y + v.z*v.z + v.w*v.w;
    #pragma unroll
    for (int o = 16; o > 0; o >>= 1) {
        s  += __shfl_down_sync(0xffffffffu, s,  o);
        ss += __shfl_down_sync(0xffffffffu, ss, o);
    }
    const int lane = t & 31, w = t >> 5;
    if (lane == 0) { sm[w] = s; sm[32 + w] = ss; }
    __syncthreads();
    if (t < 32) {
        s  = (t < 8) ? sm[t]      : 0.0f;
        ss = (t < 8) ? sm[32 + t] : 0.0f;
        #pragma unroll
        for (int o = 4; o > 0; o >>= 1) {
            s  += __shfl_down_sync(0xffffffffu, s,  o);
            ss += __shfl_down_sync(0xffffffffu, ss, o);
        }
        if (t == 0) { sm[0] = s; sm[32] = ss; }
    }
    __syncthreads();
    const float mu   = sm[0]  * (1.0f / DMODEL);
    const float var  = sm[32] * (1.0f / DMODEL) - mu * mu;
    const float rstd = rsqrtf(var + 1e-5f);

    const float4 g = ((const float4*)gamma)[t];
    const float4 b = ((const float4*)beta)[t];
    float4 o4;
    o4.x = (v.x - mu) * rstd * g.x + b.x;
    o4.y = (v.y - mu) * rstd * g.y + b.y;
    o4.z = (v.z - mu) * rstd * g.z + b.z;
    o4.w = (v.w - mu) * rstd * g.w + b.w;
    ((float4*)(out + (size_t)row * DMODEL))[t] = o4;
}

// ---------------------------------------------------------------------------
// Row softmax over 4096 elements
// ---------------------------------------------------------------------------
__global__ void __launch_bounds__(256)
softmax_kernel(float* __restrict__ s)
{
    __shared__ float sm[8];
    const int row = blockIdx.x;
    const int t = threadIdx.x;
    float4* p = (float4*)(s + (size_t)row * SEQ);

    float4 v[4];
    float m = -3.402823e38f;
    #pragma unroll
    for (int i = 0; i < 4; i++) {
        v[i] = p[t + 256 * i];
        m = fmaxf(m, fmaxf(fmaxf(v[i].x, v[i].y), fmaxf(v[i].z, v[i].w)));
    }
    #pragma unroll
    for (int o = 16; o > 0; o >>= 1) m = fmaxf(m, __shfl_xor_sync(0xffffffffu, m, o));
    const int lane = t & 31, w = t >> 5;
    if (lane == 0) sm[w] = m;
    __syncthreads();
    float mb = sm[0];
    #pragma unroll
    for (int i = 1; i < 8; i++) mb = fmaxf(mb, sm[i]);
    __syncthreads();

    float sum = 0.0f;
    #pragma unroll
    for (int i = 0; i < 4; i++) {
        v[i].x = expf(v[i].x - mb); v[i].y = expf(v[i].y - mb);
        v[i].z = expf(v[i].z - mb); v[i].w = expf(v[i].w - mb);
        sum += v[i].x + v[i].y + v[i].z + v[i].w;
    }
    #pragma unroll
    for (int o = 16; o > 0; o >>= 1) sum += __shfl_xor_sync(0xffffffffu, sum, o);
    if (lane == 0) sm[w] = sum;
    __syncthreads();
    float tot = 0.0f;
    #pragma unroll
    for (int i = 0; i < 8; i++) tot += sm[i];
    const float inv = 1.0f / tot;

    #pragma unroll
    for (int i = 0; i < 4; i++) {
        v[i].x *= inv; v[i].y *= inv; v[i].z *= inv; v[i].w *= inv;
        p[t + 256 * i] = v[i];
    }
}

// ---------------------------------------------------------------------------
// tf32 tensor-core GEMM: C = alpha * A @ op(B) [+bias][GELU][+resid]
//   A [M,K] row-major.  NN: B [K,N] row-major.  TB: B stored [N,K] row-major.
//   128x128 block tile, BK=16, 8 warps (64x32 warp tile), m16n8k8 tf32 MMA,
//   cp.async double-buffered smem, conflict-free padded strides.
// ---------------------------------------------------------------------------
template<bool TB, bool GELU, bool RESID>
__global__ void __launch_bounds__(256, 2)
gemm_tf32(const float* __restrict__ A, const float* __restrict__ Bm,
          const float* __restrict__ bias, const float* __restrict__ resid,
          float* __restrict__ C,
          int M, int N, int K,
          long long sA, long long sB, long long sC,
          float alpha)
{
    constexpr int BK = 16;
    constexpr int AST = 20;                 // As row stride (pad 16->20, conflict-free)
    constexpr int BST = TB ? 20 : 136;      // Bs stride
    constexpr int BS_ELEMS = TB ? (128 * 20) : (BK * 136);

    __shared__ float As[2][128 * AST];
    __shared__ float Bs[2][BS_ELEMS];

    const int z = blockIdx.z;
    A  += (long long)z * sA;
    Bm += (long long)z * sB;
    C  += (long long)z * sC;

    const int bx = blockIdx.x, by = blockIdx.y;
    const int tid = threadIdx.x;
    const int lane = tid & 31;
    const int warp = tid >> 5;
    const int gid = lane >> 2;       // 0..7
    const int tig = lane & 3;        // 0..3
    const int wm0 = (warp & 1) * 64; // warp row origin in block tile
    const int wn0 = (warp >> 1) * 32;

    // gmem load coordinates (A-tile: 128 rows x 4 float4; each thread 2 float4)
    const int ar[2]  = { (tid + 0)   >> 2, (tid + 256) >> 2 };
    const int ac4[2] = { (tid + 0)   & 3,  (tid + 256) & 3  };

    float acc[4][4][4];
    #pragma unroll
    for (int i = 0; i < 4; i++)
        #pragma unroll
        for (int j = 0; j < 4; j++)
            #pragma unroll
            for (int r = 0; r < 4; r++) acc[i][j][r] = 0.0f;

    const int NT = K / BK;

    // ---- tile loader (cp.async, raw fp32) ----
    auto load_tile = [&](int t, int buf) {
        const int k0 = t * BK;
        #pragma unroll
        for (int i = 0; i < 2; i++) {
            cpa16(&As[buf][ar[i] * AST + ac4[i] * 4],
                  A + (long long)(by * 128 + ar[i]) * K + k0 + ac4[i] * 4);
        }
        if (TB) {
            #pragma unroll
            for (int i = 0; i < 2; i++) {
                cpa16(&Bs[buf][ar[i] * BST + ac4[i] * 4],
                      Bm + (long long)(bx * 128 + ar[i]) * K + k0 + ac4[i] * 4);
            }
        } else {
            #pragma unroll
            for (int i = 0; i < 2; i++) {
                const int f  = tid + 256 * i;
                const int r  = f >> 5;        // 0..15
                const int c4 = f & 31;        // 0..31
                cpa16(&Bs[buf][r * BST + c4 * 4],
                      Bm + (long long)(k0 + r) * N + bx * 128 + c4 * 4);
            }
        }
        CP_COMMIT();
    };

    load_tile(0, 0);

    for (int t = 0; t < NT; ++t) {
        if (t + 1 < NT) {
            load_tile(t + 1, (t + 1) & 1);
            CP_WAIT(1);
        } else {
            CP_WAIT(0);
        }
        __syncthreads();

        const float* Ab = As[t & 1];
        const float* Bb = Bs[t & 1];

        #pragma unroll
        for (int kk = 0; kk < 2; ++kk) {
            const int kb = kk * 8;
            unsigned af[4][4], bf[4][2];
            #pragma unroll
            for (int i = 0; i < 4; i++) {
                const float* p = Ab + (wm0 + i * 16 + gid) * AST + kb + tig;
                af[i][0] = cvt_tf32(p[0]);
                af[i][1] = cvt_tf32(p[8 * AST]);
                af[i][2] = cvt_tf32(p[4]);
                af[i][3] = cvt_tf32(p[8 * AST + 4]);
            }
            #pragma unroll
            for (int j = 0; j < 4; j++) {
                if (TB) {
                    const float* p = Bb + (wn0 + j * 8 + gid) * BST + kb + tig;
                    bf[j][0] = cvt_tf32(p[0]);
                    bf[j][1] = cvt_tf32(p[4]);
                } else {
                    const float* p = Bb + (kb + tig) * BST + wn0 + j * 8 + gid;
                    bf[j][0] = cvt_tf32(p[0]);
                    bf[j][1] = cvt_tf32(p[4 * BST]);
                }
            }
            #pragma unroll
            for (int i = 0; i < 4; i++)
                #pragma unroll
                for (int j = 0; j < 4; j++)
                    mma_tf32(acc[i][j], af[i], bf[j]);
        }
        __syncthreads();
    }

    // ---- epilogue ----
    #pragma unroll
    for (int i = 0; i < 4; i++) {
        const int row0 = by * 128 + wm0 + i * 16 + gid;
        #pragma unroll
        for (int j = 0; j < 4; j++) {
            const int col = bx * 128 + wn0 + j * 8 + tig * 2;
            float b0 = 0.0f, b1 = 0.0f;
            if (bias) { b0 = bias[col]; b1 = bias[col + 1]; }
            #pragma unroll
            for (int h = 0; h < 2; h++) {          // h=0: rows row0, h=1: row0+8
                const int row = row0 + h * 8;
                float v0 = acc[i][j][h * 2 + 0] * alpha + b0;
                float v1 = acc[i][j][h * 2 + 1] * alpha + b1;
                if (GELU) {
                    v0 = 0.5f * v0 * (1.0f + erff(v0 * 0.70710678118654752f));
                    v1 = 0.5f * v1 * (1.0f + erff(v1 * 0.70710678118654752f));
                }
                const long long off = (long long)row * N + col;
                if (RESID) { v0 += resid[off]; v1 += resid[off + 1]; }
                *(float2*)(C + off) = make_float2(v0, v1);
            }
        }
    }
}

// ---------------------------------------------------------------------------
// Launch: one transformer block
// ---------------------------------------------------------------------------
extern "C" void kernel_launch(void* const* d_in, const int* in_sizes, int n_in,
                              void* d_out, int out_size)
{
    const float* x   = (const float*)d_in[0];
    const float* wq  = (const float*)d_in[1];
    const float* bq  = (const float*)d_in[2];
    const float* wk  = (const float*)d_in[3];
    const float* bk  = (const float*)d_in[4];
    const float* wv  = (const float*)d_in[5];
    const float* bv  = (const float*)d_in[6];
    const float* wo  = (const float*)d_in[7];
    const float* bo  = (const float*)d_in[8];
    const float* w1  = (const float*)d_in[9];
    const float* b1  = (const float*)d_in[10];
    const float* w2  = (const float*)d_in[11];
    const float* b2  = (const float*)d_in[12];
    const float* g1  = (const float*)d_in[13];
    const float* be1 = (const float*)d_in[14];
    const float* g2  = (const float*)d_in[15];
    const float* be2 = (const float*)d_in[16];
    float* out = (float*)d_out;

    float *h, *q, *k, *v, *sc, *att, *x1, *mid;
    cudaGetSymbolAddress((void**)&h,   g_h);
    cudaGetSymbolAddress((void**)&q,   g_q);
    cudaGetSymbolAddress((void**)&k,   g_k);
    cudaGetSymbolAddress((void**)&v,   g_v);
    cudaGetSymbolAddress((void**)&sc,  g_sc);
    cudaGetSymbolAddress((void**)&att, g_att);
    cudaGetSymbolAddress((void**)&x1,  g_x1);
    cudaGetSymbolAddress((void**)&mid, g_mid);

    const long long sdQ = (long long)SEQ * DMODEL;
    const long long sdS = (long long)SEQ * SEQ;

    // ---- attention sub-block ----
    layernorm_kernel<<<MROWS, 256>>>(x, g1, be1, h);

    dim3 gD(DMODEL / 128, MROWS / 128, 1);
    gemm_tf32<false, false, false><<<gD, 256>>>(h, wq, bq, nullptr, q,
        MROWS, DMODEL, DMODEL, 0, 0, 0, 1.0f);
    gemm_tf32<false, false, false><<<gD, 256>>>(h, wk, bk, nullptr, k,
        MROWS, DMODEL, DMODEL, 0, 0, 0, 1.0f);
    gemm_tf32<false, false, false><<<gD, 256>>>(h, wv, bv, nullptr, v,
        MROWS, DMODEL, DMODEL, 0, 0, 0, 1.0f);

    // scores = (Q @ K^T) / sqrt(D), batched over B
    dim3 gS(SEQ / 128, SEQ / 128, NBATCH);
    gemm_tf32<true, false, false><<<gS, 256>>>(q, k, nullptr, nullptr, sc,
        SEQ, SEQ, DMODEL, sdQ, sdQ, sdS, 0.03125f);

    softmax_kernel<<<MROWS, 256>>>(sc);

    // attn @ V, batched over B
    dim3 gAV(DMODEL / 128, SEQ / 128, NBATCH);
    gemm_tf32<false, false, false><<<gAV, 256>>>(sc, v, nullptr, nullptr, att,
        SEQ, DMODEL, SEQ, sdS, sdQ, sdQ, 1.0f);

    // x1 = x + attn_out @ Wo + bo
    gemm_tf32<false, false, true><<<gD, 256>>>(att, wo, bo, x, x1,
        MROWS, DMODEL, DMODEL, 0, 0, 0, 1.0f);

    // ---- FFN sub-block ----
    layernorm_kernel<<<MROWS, 256>>>(x1, g2, be2, h);

    dim3 gF1(HDIM / 128, MROWS / 128, 1);
    gemm_tf32<false, true, false><<<gF1, 256>>>(h, w1, b1, nullptr, mid,
        MROWS, HDIM, DMODEL, 0, 0, 0, 1.0f);

    // out = x1 + GELU(h@w1+b1) @ w2 + b2
    gemm_tf32<false, false, true><<<gD, 256>>>(mid, w2, b2, x1, out,
        MROWS, DMODEL, HDIM, 0, 0, 0, 1.0f);
}